// round 10
// baseline (speedup 1.0000x reference)
#include <cuda_runtime.h>
#include <math.h>

// ---------------- tuning ----------------
#define LCH  16     // samples per chunk (one chunk per thread)
#define WARM 48     // warmup (dominant perturbed pole ~0.844; <2e-5 transient)
#define TPB  64     // 2 warps/block -> 1024 blocks, 2048 warps total
#define NCH  6      // max hop rows per block region (1074 samples -> <=4)

__global__ void __launch_bounds__(TPB)
phaser_all(const float* __restrict__ x,
           const float* __restrict__ g1, const float* __restrict__ g2,
           const float* __restrict__ depth, const float* __restrict__ bias,
           const float* __restrict__ lfo_omega, const float* __restrict__ lfo_phi,
           const float* __restrict__ lfo_r_logit,
           const float* __restrict__ W_in, const float* __restrict__ b_in,
           const float* __restrict__ W_h, const float* __restrict__ b_h,
           const float* __restrict__ W_out, const float* __restrict__ b_out,
           const float* __restrict__ bq_dc, const float* __restrict__ bq_ff,
           const float* __restrict__ bq_fb,
           float* __restrict__ out, int N, int H, int out_size)
{
    constexpr int REGN = TPB * LCH + WARM + 2;     // 1074
    constexpr int PAYN = TPB * LCH;                // 1024
    __shared__ float xs[REGN + (REGN >> 4) + 8];   // pad every 16 -> stride 17
    __shared__ float ys[PAYN + (PAYN >> 4) + 8];   // staged output (padded)
    __shared__ float sc[NCH * 10];                 // per hop: cb[0..4], cd[0..4]
    __shared__ float mh[2][NCH * 16];              // MLP hidden ping-pong

    const int blockFirst      = blockIdx.x * TPB;  // first chunk id
    const int blockSampleBase = blockFirst * LCH;
    const int regionStart     = blockSampleBase - WARM - 2;
    const float scaleF = (float)((double)(H - 1) / (double)(N - 1));
    const int Hm2 = (H - 2) > 0 ? (H - 2) : 0;

    // ---- stage x into shared (coalesced; zeros outside [0,N)) ----
    for (int j = threadIdx.x; j < REGN; j += TPB) {
        int g = regionStart + j;
        xs[j + (j >> 4)] = (g >= 0 && g < N) ? x[g] : 0.f;
    }

    // ---- hop-row range this block needs ----
    int nmin = regionStart + 2; if (nmin < 0) nmin = 0;
    int nmaxx = blockSampleBase + PAYN; if (nmaxx > N) nmaxx = N;
    int i0min = (int)floorf((float)nmin * scaleF);
    if (i0min < 0) i0min = 0; if (i0min > Hm2) i0min = Hm2;
    int i0max = (int)floorf((float)(nmaxx - 1) * scaleF);
    if (i0max < 0) i0max = 0; if (i0max > Hm2) i0max = Hm2;
    const int h0 = i0min;
    int nh = i0max + 2 - h0; if (nh > NCH) nh = NCH;
    const int nwork = nh * 16;

    // ---- parallel MLP: layer 0 ----
    {
        float r    = 1.f / (1.f + expf(-lfo_r_logit[0]));
        float logr = logf(r);
        float om = lfo_omega[0], phi = lfo_phi[0];
        for (int w = threadIdx.x; w < nwork; w += TPB) {
            int hop = w >> 4, u = w & 15;
            float tf  = (float)(h0 + hop);
            float amp = expf(tf * logr);            // r^t
            float ph  = om * tf + phi;
            float l0 = amp * cosf(ph), l1 = amp * sinf(ph);
            mh[0][w] = tanhf(l0 * W_in[u] + l1 * W_in[16 + u] + b_in[u]);
        }
    }
    __syncthreads();
#pragma unroll
    for (int lay = 0; lay < 2; lay++) {
        for (int w = threadIdx.x; w < nwork; w += TPB) {
            int hop = w >> 4, u = w & 15;
            const float* hv = &mh[lay & 1][hop << 4];
            float s = b_h[lay * 16 + u];
#pragma unroll
            for (int i = 0; i < 16; i++)
                s = fmaf(hv[i], W_h[lay * 256 + i * 16 + u], s);
            mh[(lay & 1) ^ 1][w] = tanhf(s);
        }
        __syncthreads();
    }
    // ---- output layer + allpass coefficient rows (one thread per hop) ----
    if (threadIdx.x < nh) {
        int t = h0 + threadIdx.x;
        const float* hv = &mh[0][threadIdx.x << 4];
        float s = b_out[0];
#pragma unroll
        for (int i = 0; i < 16; i++) s = fmaf(hv[i], W_out[i], s);
        float ws = tanhf(s);
        float dd = bias[0] + depth[0] * 0.5f * (1.f + ws);
        float td = tanf(dd);
        float p  = tanhf((1.f - td) / (1.f + td));
        float p2 = p * p, p3 = p2 * p, p4 = p2 * p2;
        float bap[5] = { p4, -4.f * p3, 6.f * p2, -4.f * p, 1.f };
        float aap[5] = { 1.f, -4.f * p, 6.f * p2, -4.f * p3, p4 };
        float ag2 = fabsf(g2[0]);
        float den0 = aap[0] - ag2 * bap[0];
        float* row = sc + threadIdx.x * 10;
#pragma unroll
        for (int k = 0; k < 5; k++) {
            float dk = aap[k] - ag2 * bap[k];
            row[k]     = bap[k] / den0;
            row[5 + k] = dk / den0;
        }
        if (N + t < out_size) out[N + t] = p;       // second output: p (H,)
        if (t == H - 1 && blockIdx.x == gridDim.x - 1)
            for (int q2 = N + H; q2 < out_size; q2++) out[q2] = p;
    }
    __syncthreads();

    // ---- per-thread chunk ----
    const int c     = blockFirst + threadIdx.x;
    const int start = c * LCH;
    if (start < N) {
        int nstart = start - WARM; if (nstart < 0) nstart = 0;
        int nend   = start + LCH;  if (nend > N)   nend = N;

        const float b0  = bq_dc[0], b1c = bq_ff[0], b2c = bq_ff[1];
        const float a1  = 2.f * tanhf(bq_fb[0]);
        const float aa1 = fabsf(a1);
        const float a2  = ((2.f - aa1) * tanhf(bq_fb[1]) + aa1) * 0.5f;
        const float g1v = g1[0];
        const float sF1 = scaleF, sF2 = 2.f * scaleF, sF3 = 3.f * scaleF,
                    sF4 = 4.f * scaleF;

        int j = nstart - regionStart;              // xs logical index
        float x1 = xs[(j - 1) + ((j - 1) >> 4)];
        float x2 = xs[(j - 2) + ((j - 2) >> 4)];
        float f1 = 0.f, f2 = 0.f, f3 = 0.f, f4 = 0.f;
        float y1 = 0.f, y2v = 0.f, y3 = 0.f, y4 = 0.f;

        float cb00,cb01,cb02,cb03,cb04, cbd0,cbd1,cbd2,cbd3,cbd4;
        float cd01,cd02,cd03,cd04, cdd1,cdd2,cdd3,cdd4;
        int i0;
        const float* rw;
        float fr, frLim;

#define RELOAD_ROWS()                                                          \
    {                                                                          \
        cb00 = rw[0];  cb01 = rw[1];  cb02 = rw[2];  cb03 = rw[3];  cb04 = rw[4]; \
        cd01 = rw[6];  cd02 = rw[7];  cd03 = rw[8];  cd04 = rw[9];             \
        cbd0 = rw[10] - cb00; cbd1 = rw[11] - cb01; cbd2 = rw[12] - cb02;      \
        cbd3 = rw[13] - cb03; cbd4 = rw[14] - cb04;                            \
        cdd1 = rw[16] - cd01; cdd2 = rw[17] - cd02;                            \
        cdd3 = rw[18] - cd03; cdd4 = rw[19] - cd04;                            \
        frLim = (i0 < Hm2) ? 1.0f : 1e30f;                                     \
    }

        {
            float pos0 = (float)nstart * scaleF;   // exact reference seed
            i0 = (int)floorf(pos0);
            i0 = i0 < 0 ? 0 : (i0 > Hm2 ? Hm2 : i0);
            rw = sc + (i0 - h0) * 10;
            RELOAD_ROWS();
            fr = pos0 - (float)i0;
        }

        // one step (no crossing check here; FRK = fr + k*scaleF)
#define STEP(FRK, XV, XM1, XM2, H1, H2, H3, H4, HN, Y1, Y2, Y3, Y4, YN, K, DOST, Q) \
    {                                                                          \
        int jj = j + (K);                                                      \
        XV = xs[jj + (jj >> 4)];                                               \
        float v1 = fmaf(b2c, XM2, fmaf(b1c, XM1, b0 * XV));                    \
        HN = fmaf(-a2, H2, fmaf(-a1, H1, v1));                                 \
        float c0 = fmaf(FRK, cbd0, cb00);                                      \
        float c1 = fmaf(FRK, cbd1, cb01);                                      \
        float c2 = fmaf(FRK, cbd2, cb02);                                      \
        float c3 = fmaf(FRK, cbd3, cb03);                                      \
        float c4 = fmaf(FRK, cbd4, cb04);                                      \
        float v = fmaf(c0, HN, fmaf(c1, H1, fmaf(c2, H2, fmaf(c3, H3, c4 * H4)))); \
        float d1 = fmaf(FRK, cdd1, cd01);                                      \
        float d2 = fmaf(FRK, cdd2, cd02);                                      \
        float d3 = fmaf(FRK, cdd3, cd03);                                      \
        float d4 = fmaf(FRK, cdd4, cd04);                                      \
        YN = fmaf(-d1, Y1, v - fmaf(d2, Y2, fmaf(d3, Y3, d4 * Y4)));           \
        if (DOST) {                                                            \
            int qq = (Q) + (K);                                                \
            ys[qq + (qq >> 4)] = fmaf(g1v, HN, YN);                            \
        }                                                                      \
    }

        // group of 4: crossing check once (<=3-step extrapolation, negligible)
#define GROUP4(DOST, Q)                                                        \
    {                                                                          \
        if (fr >= frLim) {                                                     \
            i0++; rw += 10;                                                    \
            RELOAD_ROWS();                                                     \
            fr -= 1.0f;                                                        \
        }                                                                      \
        float fr1 = fr + sF1, fr2 = fr + sF2, fr3 = fr + sF3;                  \
        float xa, xb, xc, xd, ha, hb, hc, hd, ya, yb, yc, yd;                  \
        STEP(fr,  xa, x1, x2, f1, f2, f3, f4, ha, y1, y2v, y3, y4, ya, 0, DOST, Q) \
        STEP(fr1, xb, xa, x1, ha, f1, f2, f3, hb, ya, y1, y2v, y3, yb, 1, DOST, Q) \
        STEP(fr2, xc, xb, xa, hb, ha, f1, f2, hc, yb, ya, y1, y2v, yc, 2, DOST, Q) \
        STEP(fr3, xd, xc, xb, hc, hb, ha, f1, hd, yc, yb, ya, y1, yd, 3, DOST, Q)  \
        x2 = xc; x1 = xd;                                                      \
        f4 = ha; f3 = hb; f2 = hc; f1 = hd;                                    \
        y4 = ya; y3 = yb; y2v = yc; y1 = yd;                                   \
        fr += sF4;                                                             \
        j += 4;                                                                \
    }

        int n = nstart;
        if (((nend - nstart) & 3) == 0) {
            // fast path: warmup then payload (stores into shared ys)
            for (; n < start; n += 4) GROUP4(0, 0)
            int q = threadIdx.x * LCH;
            for (; n < nend; n += 4) { GROUP4(1, q) q += 4; }
        } else {
            // generic fallback (odd tail lengths)
            int q = threadIdx.x * LCH;
            for (; n < nend; ++n) {
                if (fr >= frLim) {
                    i0++; rw += 10;
                    RELOAD_ROWS();
                    fr -= 1.0f;
                }
                float xv = xs[j + (j >> 4)];
                float v1 = fmaf(b2c, x2, fmaf(b1c, x1, b0 * xv));
                x2 = x1; x1 = xv;
                float hcur = fmaf(-a2, f2, fmaf(-a1, f1, v1));
                float c0 = fmaf(fr, cbd0, cb00);
                float c1 = fmaf(fr, cbd1, cb01);
                float c2 = fmaf(fr, cbd2, cb02);
                float c3 = fmaf(fr, cbd3, cb03);
                float c4 = fmaf(fr, cbd4, cb04);
                float v = fmaf(c0, hcur, fmaf(c1, f1, fmaf(c2, f2, fmaf(c3, f3, c4 * f4))));
                float d1 = fmaf(fr, cdd1, cd01);
                float d2 = fmaf(fr, cdd2, cd02);
                float d3 = fmaf(fr, cdd3, cd03);
                float d4 = fmaf(fr, cdd4, cd04);
                float yv = fmaf(-d1, y1, v - fmaf(d2, y2v, fmaf(d3, y3, d4 * y4)));
                y4 = y3; y3 = y2v; y2v = y1; y1 = yv;
                f4 = f3; f3 = f2; f2 = f1; f1 = hcur;
                fr += sF1;
                j++;
                if (n >= start) { ys[q + (q >> 4)] = fmaf(g1v, hcur, yv); q++; }
            }
        }
#undef GROUP4
#undef STEP
#undef RELOAD_ROWS
    }
    __syncthreads();

    // ---- coalesced epilogue: shared ys -> global out ----
    {
        const int outLim = out_size < N ? out_size : N;
        for (int idx = threadIdx.x; idx < PAYN; idx += TPB) {
            int g = blockSampleBase + idx;
            if (g < outLim) out[g] = ys[idx + (idx >> 4)];
        }
    }
}

// ---------------- launch ----------------
extern "C" void kernel_launch(void* const* d_in, const int* in_sizes, int n_in,
                              void* d_out, int out_size)
{
    const float* x      = (const float*)d_in[0];
    const float* g1     = (const float*)d_in[1];
    const float* g2     = (const float*)d_in[2];
    const float* depth  = (const float*)d_in[3];
    const float* bias   = (const float*)d_in[4];
    const float* lfo_o  = (const float*)d_in[5];
    const float* lfo_p  = (const float*)d_in[6];
    const float* lfo_r  = (const float*)d_in[7];
    const float* W_in   = (const float*)d_in[8];
    const float* b_in   = (const float*)d_in[9];
    const float* W_h    = (const float*)d_in[10];
    const float* b_h    = (const float*)d_in[11];
    const float* W_out  = (const float*)d_in[12];
    const float* b_out  = (const float*)d_in[13];
    const float* bq_dc  = (const float*)d_in[14];
    const float* bq_ff  = (const float*)d_in[15];
    const float* bq_fb  = (const float*)d_in[16];
    float* out = (float*)d_out;

    int N = in_sizes[0];
    int H = N / 551 + 1;

    int C = (N + LCH - 1) / LCH;
    int blocks = (C + TPB - 1) / TPB;
    phaser_all<<<blocks, TPB>>>(x, g1, g2, depth, bias, lfo_o, lfo_p, lfo_r,
                                W_in, b_in, W_h, b_h, W_out, b_out,
                                bq_dc, bq_ff, bq_fb,
                                out, N, H, out_size);
}

// round 12
// speedup vs baseline: 1.2765x; 1.2765x over previous
#include <cuda_runtime.h>
#include <math.h>

// ---------------- tuning ----------------
#define LCH  32     // samples per chunk (one chunk per thread)
#define WARM 48     // warmup (measured: transient ~3e-6 rel at 48)
#define TPB  32     // one warp per block -> 1024 blocks
#define NCH  6      // max hop rows per block region (1078 samples -> <=4)
#define LEAD 4      // region lead-in so per-thread j starts 4-aligned

__global__ void __launch_bounds__(TPB)
phaser_all(const float* __restrict__ x,
           const float* __restrict__ g1, const float* __restrict__ g2,
           const float* __restrict__ depth, const float* __restrict__ bias,
           const float* __restrict__ lfo_omega, const float* __restrict__ lfo_phi,
           const float* __restrict__ lfo_r_logit,
           const float* __restrict__ W_in, const float* __restrict__ b_in,
           const float* __restrict__ W_h, const float* __restrict__ b_h,
           const float* __restrict__ W_out, const float* __restrict__ b_out,
           const float* __restrict__ bq_dc, const float* __restrict__ bq_ff,
           const float* __restrict__ bq_fb,
           float* __restrict__ out, int N, int H, int out_size)
{
    constexpr int REGN = TPB * LCH + WARM + LEAD;  // 1076
    constexpr int PAYN = TPB * LCH;                // 1024
    __shared__ float xs[REGN + (REGN >> 5) + 8];   // pad every 32 -> stride 33
    __shared__ float ys[PAYN + (PAYN >> 5) + 8];   // staged output (padded)
    __shared__ float sc[NCH * 10];                 // per hop: cb[0..4], cd[0..4]
    __shared__ float mh[2][NCH * 16];              // MLP hidden ping-pong

    const int blockFirst      = blockIdx.x * TPB;  // first chunk id
    const int blockSampleBase = blockFirst * LCH;
    const int regionStart     = blockSampleBase - WARM - LEAD;
    const float scaleF = (float)((double)(H - 1) / (double)(N - 1));
    const int Hm2 = (H - 2) > 0 ? (H - 2) : 0;

    // ---- stage x into shared (coalesced; zeros outside [0,N)) ----
    for (int j = threadIdx.x; j < REGN; j += TPB) {
        int g = regionStart + j;
        xs[j + (j >> 5)] = (g >= 0 && g < N) ? x[g] : 0.f;
    }

    // ---- hop-row range this block needs ----
    int nmin = regionStart + LEAD; if (nmin < 0) nmin = 0;
    int nmaxx = blockSampleBase + PAYN; if (nmaxx > N) nmaxx = N;
    int i0min = (int)floorf((float)nmin * scaleF);
    if (i0min < 0) i0min = 0; if (i0min > Hm2) i0min = Hm2;
    int i0max = (int)floorf((float)(nmaxx - 1) * scaleF);
    if (i0max < 0) i0max = 0; if (i0max > Hm2) i0max = Hm2;
    const int h0 = i0min;
    int nh = i0max + 2 - h0; if (nh > NCH) nh = NCH;
    const int nwork = nh * 16;

    // ---- parallel MLP: layer 0 ----
    {
        float r    = 1.f / (1.f + expf(-lfo_r_logit[0]));
        float logr = logf(r);
        float om = lfo_omega[0], phi = lfo_phi[0];
        for (int w = threadIdx.x; w < nwork; w += TPB) {
            int hop = w >> 4, u = w & 15;
            float tf  = (float)(h0 + hop);
            float amp = expf(tf * logr);            // r^t
            float ph  = om * tf + phi;
            float l0 = amp * cosf(ph), l1 = amp * sinf(ph);
            mh[0][w] = tanhf(l0 * W_in[u] + l1 * W_in[16 + u] + b_in[u]);
        }
    }
    __syncthreads();
#pragma unroll
    for (int lay = 0; lay < 2; lay++) {
        for (int w = threadIdx.x; w < nwork; w += TPB) {
            int hop = w >> 4, u = w & 15;
            const float* hv = &mh[lay & 1][hop << 4];
            float s = b_h[lay * 16 + u];
#pragma unroll
            for (int i = 0; i < 16; i++)
                s = fmaf(hv[i], W_h[lay * 256 + i * 16 + u], s);
            mh[(lay & 1) ^ 1][w] = tanhf(s);
        }
        __syncthreads();
    }
    // ---- output layer + allpass coefficient rows (one thread per hop) ----
    if (threadIdx.x < nh) {
        int t = h0 + threadIdx.x;
        const float* hv = &mh[0][threadIdx.x << 4];
        float s = b_out[0];
#pragma unroll
        for (int i = 0; i < 16; i++) s = fmaf(hv[i], W_out[i], s);
        float ws = tanhf(s);
        float dd = bias[0] + depth[0] * 0.5f * (1.f + ws);
        float td = tanf(dd);
        float p  = tanhf((1.f - td) / (1.f + td));
        float p2 = p * p, p3 = p2 * p, p4 = p2 * p2;
        float bap[5] = { p4, -4.f * p3, 6.f * p2, -4.f * p, 1.f };
        float aap[5] = { 1.f, -4.f * p, 6.f * p2, -4.f * p3, p4 };
        float ag2 = fabsf(g2[0]);
        float den0 = aap[0] - ag2 * bap[0];
        float* row = sc + threadIdx.x * 10;
#pragma unroll
        for (int k = 0; k < 5; k++) {
            float dk = aap[k] - ag2 * bap[k];
            row[k]     = bap[k] / den0;
            row[5 + k] = dk / den0;
        }
        if (N + t < out_size) out[N + t] = p;       // second output: p (H,)
        if (t == H - 1 && blockIdx.x == gridDim.x - 1)
            for (int q2 = N + H; q2 < out_size; q2++) out[q2] = p;
    }
    __syncthreads();

    // ---- per-thread chunk ----
    const int c     = blockFirst + threadIdx.x;
    const int start = c * LCH;
    if (start < N) {
        int nstart = start - WARM; if (nstart < 0) nstart = 0;
        int nend   = start + LCH;  if (nend > N)   nend = N;

        const float b0  = bq_dc[0], b1c = bq_ff[0], b2c = bq_ff[1];
        const float a1  = 2.f * tanhf(bq_fb[0]);
        const float aa1 = fabsf(a1);
        const float a2  = ((2.f - aa1) * tanhf(bq_fb[1]) + aa1) * 0.5f;
        const float g1v = g1[0];
        const float sF1 = scaleF, sF2 = 2.f * scaleF, sF3 = 3.f * scaleF,
                    sF4 = 4.f * scaleF;

        int j = nstart - regionStart;              // 4-aligned for interior chunks
        float x1 = xs[(j - 1) + ((j - 1) >> 5)];
        float x2 = xs[(j - 2) + ((j - 2) >> 5)];
        float f1 = 0.f, f2 = 0.f, f3 = 0.f, f4 = 0.f;
        float y1 = 0.f, y2v = 0.f, y3 = 0.f, y4 = 0.f;

        float cb00,cb01,cb02,cb03,cb04, cbd0,cbd1,cbd2,cbd3,cbd4;
        float cd01,cd02,cd03,cd04, cdd1,cdd2,cdd3,cdd4;
        int i0;
        const float* rw;
        float fr, frLim;

#define RELOAD_ROWS()                                                          \
    {                                                                          \
        cb00 = rw[0];  cb01 = rw[1];  cb02 = rw[2];  cb03 = rw[3];  cb04 = rw[4]; \
        cd01 = rw[6];  cd02 = rw[7];  cd03 = rw[8];  cd04 = rw[9];             \
        cbd0 = rw[10] - cb00; cbd1 = rw[11] - cb01; cbd2 = rw[12] - cb02;      \
        cbd3 = rw[13] - cb03; cbd4 = rw[14] - cb04;                            \
        cdd1 = rw[16] - cd01; cdd2 = rw[17] - cd02;                            \
        cdd3 = rw[18] - cd03; cdd4 = rw[19] - cd04;                            \
        frLim = (i0 < Hm2) ? 1.0f : 1e30f;                                     \
    }

        {
            float pos0 = (float)nstart * scaleF;   // exact reference seed
            i0 = (int)floorf(pos0);
            i0 = i0 < 0 ? 0 : (i0 > Hm2 ? Hm2 : i0);
            rw = sc + (i0 - h0) * 10;
            RELOAD_ROWS();
            fr = pos0 - (float)i0;
        }

        // one step; JP = padded shared index (consecutive within a group)
#define STEP(FRK, JP, XV, XM1, XM2, H1, H2, H3, H4, HN, Y1, Y2, Y3, Y4, YN, K, DOST, Q) \
    {                                                                          \
        XV = xs[(JP) + (K)];                                                   \
        float v1 = fmaf(b2c, XM2, fmaf(b1c, XM1, b0 * XV));                    \
        HN = fmaf(-a2, H2, fmaf(-a1, H1, v1));                                 \
        float c0 = fmaf(FRK, cbd0, cb00);                                      \
        float c1 = fmaf(FRK, cbd1, cb01);                                      \
        float c2 = fmaf(FRK, cbd2, cb02);                                      \
        float c3 = fmaf(FRK, cbd3, cb03);                                      \
        float c4 = fmaf(FRK, cbd4, cb04);                                      \
        float v = fmaf(c0, HN, fmaf(c1, H1, fmaf(c2, H2, fmaf(c3, H3, c4 * H4)))); \
        float d1 = fmaf(FRK, cdd1, cd01);                                      \
        float d2 = fmaf(FRK, cdd2, cd02);                                      \
        float d3 = fmaf(FRK, cdd3, cd03);                                      \
        float d4 = fmaf(FRK, cdd4, cd04);                                      \
        YN = fmaf(-d1, Y1, v - fmaf(d2, Y2, fmaf(d3, Y3, d4 * Y4)));           \
        if (DOST) {                                                            \
            int qq = (Q) + (K);                                                \
            ys[qq + (qq >> 5)] = fmaf(g1v, HN, YN);                            \
        }                                                                      \
    }

        // group of 4: crossing check + padded index once per group
#define GROUP4(DOST, Q)                                                        \
    {                                                                          \
        if (fr >= frLim) {                                                     \
            i0++; rw += 10;                                                    \
            RELOAD_ROWS();                                                     \
            fr -= 1.0f;                                                        \
        }                                                                      \
        int jp = j + (j >> 5);                                                 \
        float fr1 = fr + sF1, fr2 = fr + sF2, fr3 = fr + sF3;                  \
        float xa, xb, xc, xd, ha, hb, hc, hd, ya, yb, yc, yd;                  \
        STEP(fr,  jp, xa, x1, x2, f1, f2, f3, f4, ha, y1, y2v, y3, y4, ya, 0, DOST, Q) \
        STEP(fr1, jp, xb, xa, x1, ha, f1, f2, f3, hb, ya, y1, y2v, y3, yb, 1, DOST, Q) \
        STEP(fr2, jp, xc, xb, xa, hb, ha, f1, f2, hc, yb, ya, y1, y2v, yc, 2, DOST, Q) \
        STEP(fr3, jp, xd, xc, xb, hc, hb, ha, f1, hd, yc, yb, ya, y1, yd, 3, DOST, Q)  \
        x2 = xc; x1 = xd;                                                      \
        f4 = ha; f3 = hb; f2 = hc; f1 = hd;                                    \
        y4 = ya; y3 = yb; y2v = yc; y1 = yd;                                   \
        fr += sF4;                                                             \
        j += 4;                                                                \
    }

        int n = nstart;
        if (((nend - nstart) & 3) == 0 && (j & 3) == 0) {
            // fast path: 4-aligned j, lengths multiple of 4
            for (; n < start; n += 4) GROUP4(0, 0)
            int q = threadIdx.x * LCH;
            for (; n < nend; n += 4) { GROUP4(1, q) q += 4; }
        } else {
            // generic fallback (boundary chunks)
            int q = threadIdx.x * LCH;
            for (; n < nend; ++n) {
                if (fr >= frLim) {
                    i0++; rw += 10;
                    RELOAD_ROWS();
                    fr -= 1.0f;
                }
                float xv = xs[j + (j >> 5)];
                float v1 = fmaf(b2c, x2, fmaf(b1c, x1, b0 * xv));
                x2 = x1; x1 = xv;
                float hcur = fmaf(-a2, f2, fmaf(-a1, f1, v1));
                float c0 = fmaf(fr, cbd0, cb00);
                float c1 = fmaf(fr, cbd1, cb01);
                float c2 = fmaf(fr, cbd2, cb02);
                float c3 = fmaf(fr, cbd3, cb03);
                float c4 = fmaf(fr, cbd4, cb04);
                float v = fmaf(c0, hcur, fmaf(c1, f1, fmaf(c2, f2, fmaf(c3, f3, c4 * f4))));
                float d1 = fmaf(fr, cdd1, cd01);
                float d2 = fmaf(fr, cdd2, cd02);
                float d3 = fmaf(fr, cdd3, cd03);
                float d4 = fmaf(fr, cdd4, cd04);
                float yv = fmaf(-d1, y1, v - fmaf(d2, y2v, fmaf(d3, y3, d4 * y4)));
                y4 = y3; y3 = y2v; y2v = y1; y1 = yv;
                f4 = f3; f3 = f2; f2 = f1; f1 = hcur;
                fr += sF1;
                j++;
                if (n >= start) { ys[q + (q >> 5)] = fmaf(g1v, hcur, yv); q++; }
            }
        }
#undef GROUP4
#undef STEP
#undef RELOAD_ROWS
    }
    __syncthreads();

    // ---- coalesced epilogue: shared ys -> global out ----
    {
        const int outLim = out_size < N ? out_size : N;
        for (int idx = threadIdx.x; idx < PAYN; idx += TPB) {
            int g = blockSampleBase + idx;
            if (g < outLim) out[g] = ys[idx + (idx >> 5)];
        }
    }
}

// ---------------- launch ----------------
extern "C" void kernel_launch(void* const* d_in, const int* in_sizes, int n_in,
                              void* d_out, int out_size)
{
    const float* x      = (const float*)d_in[0];
    const float* g1     = (const float*)d_in[1];
    const float* g2     = (const float*)d_in[2];
    const float* depth  = (const float*)d_in[3];
    const float* bias   = (const float*)d_in[4];
    const float* lfo_o  = (const float*)d_in[5];
    const float* lfo_p  = (const float*)d_in[6];
    const float* lfo_r  = (const float*)d_in[7];
    const float* W_in   = (const float*)d_in[8];
    const float* b_in   = (const float*)d_in[9];
    const float* W_h    = (const float*)d_in[10];
    const float* b_h    = (const float*)d_in[11];
    const float* W_out  = (const float*)d_in[12];
    const float* b_out  = (const float*)d_in[13];
    const float* bq_dc  = (const float*)d_in[14];
    const float* bq_ff  = (const float*)d_in[15];
    const float* bq_fb  = (const float*)d_in[16];
    float* out = (float*)d_out;

    int N = in_sizes[0];
    int H = N / 551 + 1;

    int C = (N + LCH - 1) / LCH;
    int blocks = (C + TPB - 1) / TPB;
    phaser_all<<<blocks, TPB>>>(x, g1, g2, depth, bias, lfo_o, lfo_p, lfo_r,
                                W_in, b_in, W_h, b_h, W_out, b_out,
                                bq_dc, bq_ff, bq_fb,
                                out, N, H, out_size);
}

// round 13
// speedup vs baseline: 1.2848x; 1.0065x over previous
#include <cuda_runtime.h>
#include <math.h>

// ---------------- tuning ----------------
#define LCH  32     // samples per chunk (one chunk per thread)
#define WARM 32     // warmup (measured transient ~3e-5 rel at 32)
#define TPB  32     // one warp per block -> 1024 blocks
#define NCH  6      // max hop rows per block region (<=4 actual)
#define LEAD 4      // region lead-in so per-thread j starts 4-aligned

__global__ void __launch_bounds__(TPB)
phaser_all(const float* __restrict__ x,
           const float* __restrict__ g1, const float* __restrict__ g2,
           const float* __restrict__ depth, const float* __restrict__ bias,
           const float* __restrict__ lfo_omega, const float* __restrict__ lfo_phi,
           const float* __restrict__ lfo_r_logit,
           const float* __restrict__ W_in, const float* __restrict__ b_in,
           const float* __restrict__ W_h, const float* __restrict__ b_h,
           const float* __restrict__ W_out, const float* __restrict__ b_out,
           const float* __restrict__ bq_dc, const float* __restrict__ bq_ff,
           const float* __restrict__ bq_fb,
           float* __restrict__ out, int N, int H, int out_size)
{
    constexpr int REGN = TPB * LCH + WARM + LEAD;  // 1060
    constexpr int PAYN = TPB * LCH;                // 1024
    __shared__ float xs[REGN + (REGN >> 5) + 8];   // pad every 32 -> stride 33
    __shared__ float ys[PAYN + (PAYN >> 5) + 8];   // staged output (padded)
    __shared__ float sc[NCH * 10];                 // per hop: cb[0..4], cd[0..4]
    __shared__ float mh[2][NCH * 16];              // MLP hidden ping-pong

    const int blockFirst      = blockIdx.x * TPB;  // first chunk id
    const int blockSampleBase = blockFirst * LCH;
    const int regionStart     = blockSampleBase - WARM - LEAD;
    const float scaleF = (float)((double)(H - 1) / (double)(N - 1));
    const int Hm2 = (H - 2) > 0 ? (H - 2) : 0;

    // ---- stage x into shared (coalesced; zeros outside [0,N)) ----
    for (int j = threadIdx.x; j < REGN; j += TPB) {
        int g = regionStart + j;
        xs[j + (j >> 5)] = (g >= 0 && g < N) ? x[g] : 0.f;
    }

    // ---- hop-row range this block needs ----
    int nmin = regionStart + LEAD; if (nmin < 0) nmin = 0;
    int nmaxx = blockSampleBase + PAYN; if (nmaxx > N) nmaxx = N;
    int i0min = (int)floorf((float)nmin * scaleF);
    if (i0min < 0) i0min = 0; if (i0min > Hm2) i0min = Hm2;
    int i0max = (int)floorf((float)(nmaxx - 1) * scaleF);
    if (i0max < 0) i0max = 0; if (i0max > Hm2) i0max = Hm2;
    const int h0 = i0min;
    int nh = i0max + 2 - h0; if (nh > NCH) nh = NCH;
    const int nwork = nh * 16;

    // ---- parallel MLP: layer 0 ----
    {
        float r    = 1.f / (1.f + expf(-lfo_r_logit[0]));
        float logr = logf(r);
        float om = lfo_omega[0], phi = lfo_phi[0];
        for (int w = threadIdx.x; w < nwork; w += TPB) {
            int hop = w >> 4, u = w & 15;
            float tf  = (float)(h0 + hop);
            float amp = expf(tf * logr);            // r^t
            float ph  = om * tf + phi;
            float l0 = amp * cosf(ph), l1 = amp * sinf(ph);
            mh[0][w] = tanhf(l0 * W_in[u] + l1 * W_in[16 + u] + b_in[u]);
        }
    }
    __syncthreads();
#pragma unroll
    for (int lay = 0; lay < 2; lay++) {
        for (int w = threadIdx.x; w < nwork; w += TPB) {
            int hop = w >> 4, u = w & 15;
            const float* hv = &mh[lay & 1][hop << 4];
            float s = b_h[lay * 16 + u];
#pragma unroll
            for (int i = 0; i < 16; i++)
                s = fmaf(hv[i], W_h[lay * 256 + i * 16 + u], s);
            mh[(lay & 1) ^ 1][w] = tanhf(s);
        }
        __syncthreads();
    }
    // ---- output layer + allpass coefficient rows (one thread per hop) ----
    if (threadIdx.x < nh) {
        int t = h0 + threadIdx.x;
        const float* hv = &mh[0][threadIdx.x << 4];
        float s = b_out[0];
#pragma unroll
        for (int i = 0; i < 16; i++) s = fmaf(hv[i], W_out[i], s);
        float ws = tanhf(s);
        float dd = bias[0] + depth[0] * 0.5f * (1.f + ws);
        float td = tanf(dd);
        float p  = tanhf((1.f - td) / (1.f + td));
        float p2 = p * p, p3 = p2 * p, p4 = p2 * p2;
        float bap[5] = { p4, -4.f * p3, 6.f * p2, -4.f * p, 1.f };
        float aap[5] = { 1.f, -4.f * p, 6.f * p2, -4.f * p3, p4 };
        float ag2 = fabsf(g2[0]);
        float den0 = aap[0] - ag2 * bap[0];
        float* row = sc + threadIdx.x * 10;
#pragma unroll
        for (int k = 0; k < 5; k++) {
            float dk = aap[k] - ag2 * bap[k];
            row[k]     = bap[k] / den0;
            row[5 + k] = dk / den0;
        }
        if (N + t < out_size) out[N + t] = p;       // second output: p (H,)
        if (t == H - 1 && blockIdx.x == gridDim.x - 1)
            for (int q2 = N + H; q2 < out_size; q2++) out[q2] = p;
    }
    __syncthreads();

    // ---- per-thread chunk ----
    const int c     = blockFirst + threadIdx.x;
    const int start = c * LCH;
    if (start < N) {
        int nstart = start - WARM; if (nstart < 0) nstart = 0;
        int nend   = start + LCH;  if (nend > N)   nend = N;

        const float b0  = bq_dc[0], b1c = bq_ff[0], b2c = bq_ff[1];
        const float a1  = 2.f * tanhf(bq_fb[0]);
        const float aa1 = fabsf(a1);
        const float a2  = ((2.f - aa1) * tanhf(bq_fb[1]) + aa1) * 0.5f;
        const float g1v = g1[0];
        const float sF1 = scaleF, sF4 = 4.f * scaleF;
        const float sFm = 1.5f * scaleF;           // group-midpoint offset

        int j = nstart - regionStart;              // 4-aligned for interior chunks
        float x1 = xs[(j - 1) + ((j - 1) >> 5)];
        float x2 = xs[(j - 2) + ((j - 2) >> 5)];
        float f1 = 0.f, f2 = 0.f, f3 = 0.f, f4 = 0.f;
        float y1 = 0.f, y2v = 0.f, y3 = 0.f, y4 = 0.f;

        float cb00,cb01,cb02,cb03,cb04, cbd0,cbd1,cbd2,cbd3,cbd4;
        float cd01,cd02,cd03,cd04, cdd1,cdd2,cdd3,cdd4;
        int i0;
        const float* rw;
        float fr, frLim;

#define RELOAD_ROWS()                                                          \
    {                                                                          \
        cb00 = rw[0];  cb01 = rw[1];  cb02 = rw[2];  cb03 = rw[3];  cb04 = rw[4]; \
        cd01 = rw[6];  cd02 = rw[7];  cd03 = rw[8];  cd04 = rw[9];             \
        cbd0 = rw[10] - cb00; cbd1 = rw[11] - cb01; cbd2 = rw[12] - cb02;      \
        cbd3 = rw[13] - cb03; cbd4 = rw[14] - cb04;                            \
        cdd1 = rw[16] - cd01; cdd2 = rw[17] - cd02;                            \
        cdd3 = rw[18] - cd03; cdd4 = rw[19] - cd04;                            \
        frLim = (i0 < Hm2) ? 1.0f : 1e30f;                                     \
    }

        {
            float pos0 = (float)nstart * scaleF;   // exact reference seed
            i0 = (int)floorf(pos0);
            i0 = i0 < 0 ? 0 : (i0 > Hm2 ? Hm2 : i0);
            rw = sc + (i0 - h0) * 10;
            RELOAD_ROWS();
            fr = pos0 - (float)i0;
        }

        // one step with group-constant coefficients gc0..gc4 / gd1..gd4
#define STEP(JP, XV, XM1, XM2, H1, H2, H3, H4, HN, Y1, Y2, Y3, Y4, YN, K, DOST, Q) \
    {                                                                          \
        XV = xs[(JP) + (K)];                                                   \
        float v1 = fmaf(b2c, XM2, fmaf(b1c, XM1, b0 * XV));                    \
        HN = fmaf(-a2, H2, fmaf(-a1, H1, v1));                                 \
        float v = fmaf(gc0, HN, fmaf(gc1, H1, fmaf(gc2, H2, fmaf(gc3, H3, gc4 * H4)))); \
        YN = fmaf(-gd1, Y1, v - fmaf(gd2, Y2, fmaf(gd3, Y3, gd4 * Y4)));       \
        if (DOST) {                                                            \
            int qq = (Q) + (K);                                                \
            ys[qq + (qq >> 5)] = fmaf(g1v, HN, YN);                            \
        }                                                                      \
    }

        // group of 4: crossing check + midpoint coefficient eval once
#define GROUP4(DOST, Q)                                                        \
    {                                                                          \
        if (fr >= frLim) {                                                     \
            i0++; rw += 10;                                                    \
            RELOAD_ROWS();                                                     \
            fr -= 1.0f;                                                        \
        }                                                                      \
        float frm = fr + sFm;                                                  \
        float gc0 = fmaf(frm, cbd0, cb00);                                     \
        float gc1 = fmaf(frm, cbd1, cb01);                                     \
        float gc2 = fmaf(frm, cbd2, cb02);                                     \
        float gc3 = fmaf(frm, cbd3, cb03);                                     \
        float gc4 = fmaf(frm, cbd4, cb04);                                     \
        float gd1 = fmaf(frm, cdd1, cd01);                                     \
        float gd2 = fmaf(frm, cdd2, cd02);                                     \
        float gd3 = fmaf(frm, cdd3, cd03);                                     \
        float gd4 = fmaf(frm, cdd4, cd04);                                     \
        int jp = j + (j >> 5);                                                 \
        float xa, xb, xc, xd, ha, hb, hc, hd, ya, yb, yc, yd;                  \
        STEP(jp, xa, x1, x2, f1, f2, f3, f4, ha, y1, y2v, y3, y4, ya, 0, DOST, Q) \
        STEP(jp, xb, xa, x1, ha, f1, f2, f3, hb, ya, y1, y2v, y3, yb, 1, DOST, Q) \
        STEP(jp, xc, xb, xa, hb, ha, f1, f2, hc, yb, ya, y1, y2v, yc, 2, DOST, Q) \
        STEP(jp, xd, xc, xb, hc, hb, ha, f1, hd, yc, yb, ya, y1, yd, 3, DOST, Q)  \
        x2 = xc; x1 = xd;                                                      \
        f4 = ha; f3 = hb; f2 = hc; f1 = hd;                                    \
        y4 = ya; y3 = yb; y2v = yc; y1 = yd;                                   \
        fr += sF4;                                                             \
        j += 4;                                                                \
    }

        int n = nstart;
        if (((nend - nstart) & 3) == 0 && (j & 3) == 0) {
            // fast path: 4-aligned j, lengths multiple of 4
            for (; n < start; n += 4) GROUP4(0, 0)
            int q = threadIdx.x * LCH;
            for (; n < nend; n += 4) { GROUP4(1, q) q += 4; }
        } else {
            // generic fallback (boundary chunks): exact per-sample interp
            int q = threadIdx.x * LCH;
            for (; n < nend; ++n) {
                if (fr >= frLim) {
                    i0++; rw += 10;
                    RELOAD_ROWS();
                    fr -= 1.0f;
                }
                float xv = xs[j + (j >> 5)];
                float v1 = fmaf(b2c, x2, fmaf(b1c, x1, b0 * xv));
                x2 = x1; x1 = xv;
                float hcur = fmaf(-a2, f2, fmaf(-a1, f1, v1));
                float c0 = fmaf(fr, cbd0, cb00);
                float c1 = fmaf(fr, cbd1, cb01);
                float c2 = fmaf(fr, cbd2, cb02);
                float c3 = fmaf(fr, cbd3, cb03);
                float c4 = fmaf(fr, cbd4, cb04);
                float v = fmaf(c0, hcur, fmaf(c1, f1, fmaf(c2, f2, fmaf(c3, f3, c4 * f4))));
                float d1 = fmaf(fr, cdd1, cd01);
                float d2 = fmaf(fr, cdd2, cd02);
                float d3 = fmaf(fr, cdd3, cd03);
                float d4 = fmaf(fr, cdd4, cd04);
                float yv = fmaf(-d1, y1, v - fmaf(d2, y2v, fmaf(d3, y3, d4 * y4)));
                y4 = y3; y3 = y2v; y2v = y1; y1 = yv;
                f4 = f3; f3 = f2; f2 = f1; f1 = hcur;
                fr += sF1;
                j++;
                if (n >= start) { ys[q + (q >> 5)] = fmaf(g1v, hcur, yv); q++; }
            }
        }
#undef GROUP4
#undef STEP
#undef RELOAD_ROWS
    }
    __syncthreads();

    // ---- coalesced epilogue: shared ys -> global out ----
    {
        const int outLim = out_size < N ? out_size : N;
        for (int idx = threadIdx.x; idx < PAYN; idx += TPB) {
            int g = blockSampleBase + idx;
            if (g < outLim) out[g] = ys[idx + (idx >> 5)];
        }
    }
}

// ---------------- launch ----------------
extern "C" void kernel_launch(void* const* d_in, const int* in_sizes, int n_in,
                              void* d_out, int out_size)
{
    const float* x      = (const float*)d_in[0];
    const float* g1     = (const float*)d_in[1];
    const float* g2     = (const float*)d_in[2];
    const float* depth  = (const float*)d_in[3];
    const float* bias   = (const float*)d_in[4];
    const float* lfo_o  = (const float*)d_in[5];
    const float* lfo_p  = (const float*)d_in[6];
    const float* lfo_r  = (const float*)d_in[7];
    const float* W_in   = (const float*)d_in[8];
    const float* b_in   = (const float*)d_in[9];
    const float* W_h    = (const float*)d_in[10];
    const float* b_h    = (const float*)d_in[11];
    const float* W_out  = (const float*)d_in[12];
    const float* b_out  = (const float*)d_in[13];
    const float* bq_dc  = (const float*)d_in[14];
    const float* bq_ff  = (const float*)d_in[15];
    const float* bq_fb  = (const float*)d_in[16];
    float* out = (float*)d_out;

    int N = in_sizes[0];
    int H = N / 551 + 1;

    int C = (N + LCH - 1) / LCH;
    int blocks = (C + TPB - 1) / TPB;
    phaser_all<<<blocks, TPB>>>(x, g1, g2, depth, bias, lfo_o, lfo_p, lfo_r,
                                W_in, b_in, W_h, b_h, W_out, b_out,
                                bq_dc, bq_ff, bq_fb,
                                out, N, H, out_size);
}